// round 3
// baseline (speedup 1.0000x reference)
#include <cuda_runtime.h>

#define D 64
#define NMAX 50000
#define EMAX 800000

// Scratch (device globals — no allocation allowed)
__device__ float g_y[NMAX * D];     // per-node MLP1 output
__device__ float g_agg[NMAX * D];   // scatter accumulator, later mean
__device__ int   g_cnt[NMAX];

// ---------------------------------------------------------------------------
// Zero the scatter accumulators
// ---------------------------------------------------------------------------
__global__ void zero_kernel(int n) {
    int i = blockIdx.x * blockDim.x + threadIdx.x;
    if (i < n * (D / 4)) reinterpret_cast<float4*>(g_agg)[i] = make_float4(0.f, 0.f, 0.f, 0.f);
    if (i < n) g_cnt[i] = 0;
}

// ---------------------------------------------------------------------------
// dot of vector v (registers, constant-indexed) against 4 consecutive rows of
// a row-major weight matrix in smem (broadcast reads: all lanes same address).
// LEN = row segment length, STRIDE = row stride (floats).
// ---------------------------------------------------------------------------
template <int LEN, int STRIDE>
__device__ __forceinline__ float4 dot4(const float* __restrict__ w0, const float* v) {
    const float* w1 = w0 + STRIDE;
    const float* w2 = w0 + 2 * STRIDE;
    const float* w3 = w0 + 3 * STRIDE;
    float a0 = 0.f, a1 = 0.f, a2 = 0.f, a3 = 0.f;
#pragma unroll
    for (int k4 = 0; k4 < LEN / 4; k4++) {
        float4 q0 = reinterpret_cast<const float4*>(w0)[k4];
        float4 q1 = reinterpret_cast<const float4*>(w1)[k4];
        float4 q2 = reinterpret_cast<const float4*>(w2)[k4];
        float4 q3 = reinterpret_cast<const float4*>(w3)[k4];
        float b0 = v[4 * k4 + 0], b1 = v[4 * k4 + 1], b2 = v[4 * k4 + 2], b3 = v[4 * k4 + 3];
        a0 = fmaf(b0, q0.x, fmaf(b1, q0.y, fmaf(b2, q0.z, fmaf(b3, q0.w, a0))));
        a1 = fmaf(b0, q1.x, fmaf(b1, q1.y, fmaf(b2, q1.z, fmaf(b3, q1.w, a1))));
        a2 = fmaf(b0, q2.x, fmaf(b1, q2.y, fmaf(b2, q2.z, fmaf(b3, q2.w, a2))));
        a3 = fmaf(b0, q3.x, fmaf(b1, q3.y, fmaf(b2, q3.z, fmaf(b3, q3.w, a3))));
    }
    return make_float4(a0, a1, a2, a3);
}

// ---------------------------------------------------------------------------
// MLP1 per NODE (algebraic move of the per-edge MLP before the gather):
//   y = relu(x @ W1a^T) @ W1b^T
// Thread = node. Weights in smem (broadcast float4 reads). Hidden vector goes
// through a per-thread padded smem slice (dynamic j index), then is reloaded
// into constant-indexed registers for layer 2.
// ---------------------------------------------------------------------------
__global__ __launch_bounds__(128) void mlp1_kernel(
    const float* __restrict__ x, const float* __restrict__ W1a,
    const float* __restrict__ W1b, int n)
{
    extern __shared__ float smem[];
    float* sA = smem;               // W1a [64][64]
    float* sB = smem + 4096;        // W1b [64][64]
    float* sS = smem + 8192;        // scratch slices [128][65]
    int tid = threadIdx.x;
    for (int i = tid; i < 4096; i += 128) { sA[i] = W1a[i]; sB[i] = W1b[i]; }
    __syncthreads();

    int node = blockIdx.x * 128 + tid;
    if (node >= n) return;
    float* myS = sS + tid * 65;

    float xr[D];
    const float4* xp = reinterpret_cast<const float4*>(x + (size_t)node * D);
#pragma unroll
    for (int k4 = 0; k4 < D / 4; k4++) {
        float4 v = xp[k4];
        xr[4 * k4 + 0] = v.x; xr[4 * k4 + 1] = v.y;
        xr[4 * k4 + 2] = v.z; xr[4 * k4 + 3] = v.w;
    }

    // layer 1 + ReLU -> smem slice
    for (int j = 0; j < D; j += 4) {
        float4 h = dot4<64, 64>(sA + j * 64, xr);
        myS[j + 0] = fmaxf(h.x, 0.f);
        myS[j + 1] = fmaxf(h.y, 0.f);
        myS[j + 2] = fmaxf(h.z, 0.f);
        myS[j + 3] = fmaxf(h.w, 0.f);
    }
    float hr[D];
#pragma unroll
    for (int k = 0; k < D; k++) hr[k] = myS[k];

    // layer 2 -> g_y
    float4* yp = reinterpret_cast<float4*>(g_y + (size_t)node * D);
    for (int j = 0; j < D; j += 4) {
        float4 o = dot4<64, 64>(sB + j * 64, hr);
        yp[j >> 2] = o;
    }
}

// ---------------------------------------------------------------------------
// Scatter-add: 64 threads per edge, one scalar float per thread. Each warp
// issues 32 consecutive-address REDG.ADD.F32 on one destination row
// (coalesced 128B sectors at L2). edge_index is INT32 (jax downcasts int64).
// ---------------------------------------------------------------------------
__global__ void scatter_kernel(const int* __restrict__ ei, int E, int n) {
    long long t = (long long)blockIdx.x * blockDim.x + threadIdx.x;
    int e = (int)(t >> 6);
    if (e >= E) return;
    int c = (int)(t & 63);
    int row = ei[e];
    int col = ei[E + e];
    if ((unsigned)row >= (unsigned)n || (unsigned)col >= (unsigned)n) return;
    float v = g_y[(size_t)row * D + c];
    atomicAdd(g_agg + (size_t)col * D + c, v);
    if (c == 0) atomicAdd(g_cnt + col, 1);
}

// ---------------------------------------------------------------------------
// Epilogue per node (thread = node, so LayerNorm reductions are serial over
// the thread's own 64 registers — no cross-thread reduction needed):
//   agg = LN1(sum/cnt); hid = agg @ W2a[:,64:]^T           (partial)
//   t   = x + (x - agg)*w; fx = LN2(t)                     (overwrites agg regs)
//   hid = relu(hid + fx @ W2a[:,:64]^T)
//   out = hid @ W2b^T
// ---------------------------------------------------------------------------
__global__ __launch_bounds__(128) void epilogue_kernel(
    const float* __restrict__ x,
    const float* __restrict__ g1, const float* __restrict__ b1,
    const float* __restrict__ wrep,
    const float* __restrict__ g2, const float* __restrict__ b2,
    const float* __restrict__ W2a, const float* __restrict__ W2b,
    float* __restrict__ out, int n)
{
    extern __shared__ float smem[];
    float* sA = smem;                // W2a [64][128]
    float* sB = smem + 8192;         // W2b [64][64]
    float* sS = smem + 12288;        // scratch slices [128][65]
    int tid = threadIdx.x;
    for (int i = tid; i < 8192; i += 128) sA[i] = W2a[i];
    for (int i = tid; i < 4096; i += 128) sB[i] = W2b[i];
    __syncthreads();

    int node = blockIdx.x * 128 + tid;
    if (node >= n) return;
    float* myS = sS + tid * 65;

    float a[D];
    float inv = 1.0f / fmaxf((float)g_cnt[node], 1.0f);
    const float4* sp = reinterpret_cast<const float4*>(g_agg + (size_t)node * D);
#pragma unroll
    for (int k4 = 0; k4 < D / 4; k4++) {
        float4 v = sp[k4];
        a[4 * k4 + 0] = v.x * inv; a[4 * k4 + 1] = v.y * inv;
        a[4 * k4 + 2] = v.z * inv; a[4 * k4 + 3] = v.w * inv;
    }

    // LayerNorm 1 (biased var, eps=1e-5)
    {
        float m = 0.f;
#pragma unroll
        for (int k = 0; k < D; k++) m += a[k];
        m *= (1.f / D);
        float var = 0.f;
#pragma unroll
        for (int k = 0; k < D; k++) { float d = a[k] - m; var += d * d; }
        float r = rsqrtf(var * (1.f / D) + 1e-5f);
#pragma unroll
        for (int k = 0; k < D; k++) a[k] = (a[k] - m) * r * g1[k] + b1[k];
    }

    // hidden partial: agg against W2a columns [64:128)
    for (int j = 0; j < D; j += 4) {
        float4 h = dot4<64, 128>(sA + j * 128 + 64, a);
        myS[j + 0] = h.x; myS[j + 1] = h.y; myS[j + 2] = h.z; myS[j + 3] = h.w;
    }

    // t = x + (x - agg)*w  (overwrite a)
    const float4* xp = reinterpret_cast<const float4*>(x + (size_t)node * D);
#pragma unroll
    for (int k4 = 0; k4 < D / 4; k4++) {
        float4 v = xp[k4];
        a[4 * k4 + 0] = v.x + (v.x - a[4 * k4 + 0]) * wrep[4 * k4 + 0];
        a[4 * k4 + 1] = v.y + (v.y - a[4 * k4 + 1]) * wrep[4 * k4 + 1];
        a[4 * k4 + 2] = v.z + (v.z - a[4 * k4 + 2]) * wrep[4 * k4 + 2];
        a[4 * k4 + 3] = v.w + (v.w - a[4 * k4 + 3]) * wrep[4 * k4 + 3];
    }

    // LayerNorm 2 -> fx (in place)
    {
        float m = 0.f;
#pragma unroll
        for (int k = 0; k < D; k++) m += a[k];
        m *= (1.f / D);
        float var = 0.f;
#pragma unroll
        for (int k = 0; k < D; k++) { float d = a[k] - m; var += d * d; }
        float r = rsqrtf(var * (1.f / D) + 1e-5f);
#pragma unroll
        for (int k = 0; k < D; k++) a[k] = (a[k] - m) * r * g2[k] + b2[k];
    }

    // hidden += fx part (W2a columns [0:64)), ReLU
    for (int j = 0; j < D; j += 4) {
        float4 h = dot4<64, 128>(sA + j * 128, a);
        myS[j + 0] = fmaxf(myS[j + 0] + h.x, 0.f);
        myS[j + 1] = fmaxf(myS[j + 1] + h.y, 0.f);
        myS[j + 2] = fmaxf(myS[j + 2] + h.z, 0.f);
        myS[j + 3] = fmaxf(myS[j + 3] + h.w, 0.f);
    }
    float hr[D];
#pragma unroll
    for (int k = 0; k < D; k++) hr[k] = myS[k];

    // out = hidden @ W2b^T
    float4* op = reinterpret_cast<float4*>(out + (size_t)node * D);
    for (int j = 0; j < D; j += 4) {
        float4 o = dot4<64, 64>(sB + j * 64, hr);
        op[j >> 2] = o;
    }
}

// ---------------------------------------------------------------------------
// Launch
// ---------------------------------------------------------------------------
extern "C" void kernel_launch(void* const* d_in, const int* in_sizes, int n_in,
                              void* d_out, int out_size) {
    const float* x   = (const float*)d_in[0];
    const int*   ei  = (const int*)d_in[1];      // int32! (jax downcasts int64)
    const float* W1a = (const float*)d_in[2];
    const float* W1b = (const float*)d_in[3];
    const float* g1  = (const float*)d_in[4];
    const float* b1  = (const float*)d_in[5];
    const float* w   = (const float*)d_in[6];
    const float* g2  = (const float*)d_in[7];
    const float* b2  = (const float*)d_in[8];
    const float* W2a = (const float*)d_in[9];
    const float* W2b = (const float*)d_in[10];
    float* out = (float*)d_out;

    int n = in_sizes[0] / D;
    int E = in_sizes[1] / 2;

    const int MLP1_SMEM = (4096 + 4096 + 128 * 65) * 4;   // 66048 B
    const int EPI_SMEM  = (8192 + 4096 + 128 * 65) * 4;   // 82432 B
    cudaFuncSetAttribute(mlp1_kernel, cudaFuncAttributeMaxDynamicSharedMemorySize, MLP1_SMEM);
    cudaFuncSetAttribute(epilogue_kernel, cudaFuncAttributeMaxDynamicSharedMemorySize, EPI_SMEM);

    zero_kernel<<<(n * 16 + 255) / 256, 256>>>(n);
    mlp1_kernel<<<(n + 127) / 128, 128, MLP1_SMEM>>>(x, W1a, W1b, n);
    {
        long long total = (long long)E * 64;
        int blocks = (int)((total + 255) / 256);
        scatter_kernel<<<blocks, 256>>>(ei, E, n);
    }
    epilogue_kernel<<<(n + 127) / 128, 128, EPI_SMEM>>>(x, g1, b1, w, g2, b2, W2a, W2b, out, n);
}

// round 4
// speedup vs baseline: 1.0655x; 1.0655x over previous
#include <cuda_runtime.h>

#define D 64
#define NMAX 50000
#define EMAX 800000

typedef unsigned long long u64;

// Scratch (device globals — no allocation allowed). 16B-aligned for v128 access.
__device__ __align__(16) float g_y[NMAX * D];     // per-node MLP1 output
__device__ __align__(16) float g_agg[NMAX * D];   // scatter accumulator
__device__ int g_cnt[NMAX];

// ---------------------------------------------------------------------------
// Packed fp32x2 helpers (sm_100+ PTX; FFMA2 is unreachable from plain C++)
// ---------------------------------------------------------------------------
__device__ __forceinline__ u64 pack2(float lo, float hi) {
    u64 r; asm("mov.b64 %0, {%1, %2};" : "=l"(r) : "f"(lo), "f"(hi)); return r;
}
__device__ __forceinline__ u64 dup2(float s) { return pack2(s, s); }
__device__ __forceinline__ void unpack2(u64 v, float& lo, float& hi) {
    asm("mov.b64 {%0, %1}, %2;" : "=f"(lo), "=f"(hi) : "l"(v));
}
__device__ __forceinline__ u64 fma2(u64 a, u64 b, u64 c) {
    u64 d; asm("fma.rn.f32x2 %0, %1, %2, %3;" : "=l"(d) : "l"(a), "l"(b), "l"(c)); return d;
}
__device__ __forceinline__ u64 add2(u64 a, u64 b) {
    u64 d; asm("add.rn.f32x2 %0, %1, %2;" : "=l"(d) : "l"(a), "l"(b)); return d;
}
__device__ __forceinline__ u64 mul2(u64 a, u64 b) {
    u64 d; asm("mul.rn.f32x2 %0, %1, %2;" : "=l"(d) : "l"(a), "l"(b)); return d;
}
__device__ __forceinline__ u64 neg2(u64 a) { return a ^ 0x8000000080000000ULL; }

// Packed LayerNorm over 32 pairs (64 features), biased var, eps=1e-5.
__device__ __forceinline__ void layernorm_packed(u64* v, const u64* __restrict__ pg,
                                                 const u64* __restrict__ pb) {
    u64 s = 0ULL;
#pragma unroll
    for (int i = 0; i < 32; i++) s = add2(s, v[i]);
    float lo, hi; unpack2(s, lo, hi);
    float m = (lo + hi) * (1.f / 64.f);
    u64 mneg = dup2(-m);
    u64 acc = 0ULL;
#pragma unroll
    for (int i = 0; i < 32; i++) { u64 d = add2(v[i], mneg); acc = fma2(d, d, acc); }
    unpack2(acc, lo, hi);
    float r = rsqrtf((lo + hi) * (1.f / 64.f) + 1e-5f);
    u64 r2 = dup2(r);
#pragma unroll
    for (int i = 0; i < 32; i++) {
        u64 d = mul2(add2(v[i], mneg), r2);
        v[i] = fma2(d, pg[i], pb[i]);
    }
}

// ---------------------------------------------------------------------------
// Zero the scatter accumulators
// ---------------------------------------------------------------------------
__global__ void zero_kernel(int n) {
    int i = blockIdx.x * blockDim.x + threadIdx.x;
    if (i < n * (D / 4)) reinterpret_cast<float4*>(g_agg)[i] = make_float4(0.f, 0.f, 0.f, 0.f);
    if (i < n) g_cnt[i] = 0;
}

// ---------------------------------------------------------------------------
// MLP1 per node: y = relu(x @ W1a^T) @ W1b^T  (moved before gather: 16x FLOP cut)
// Dot-form for layer 1 (j-quad loop, rolled, inner fully unrolled so x2 stays
// constant-indexed); each relu'd hidden quad is immediately rank-1 accumulated
// into packed y2 registers via transposed W1b — no intermediate storage.
// ---------------------------------------------------------------------------
__global__ __launch_bounds__(128) void mlp1_kernel(
    const float* __restrict__ x, const float* __restrict__ W1a,
    const float* __restrict__ W1b, int n)
{
    __shared__ __align__(16) float sA[4096];   // W1a row-major
    __shared__ __align__(16) float sBT[4096];  // W1b^T: sBT[k*64+o] = W1b[o][k]
    int tid = threadIdx.x;
    for (int i = tid; i < 4096; i += 128) {
        sA[i] = W1a[i];
        int o = i >> 6, k = i & 63;
        sBT[k * 64 + o] = W1b[i];
    }
    __syncthreads();

    int node = blockIdx.x * 128 + tid;
    if (node >= n) return;

    u64 x2[32];
    const ulonglong2* xp = reinterpret_cast<const ulonglong2*>(x + (size_t)node * D);
#pragma unroll
    for (int q = 0; q < 16; q++) { ulonglong2 v = xp[q]; x2[2 * q] = v.x; x2[2 * q + 1] = v.y; }

    u64 y2[32];
#pragma unroll
    for (int i = 0; i < 32; i++) y2[i] = 0ULL;

    for (int jq = 0; jq < 16; jq++) {
        float h[4];
#pragma unroll
        for (int r = 0; r < 4; r++) {
            const ulonglong2* wp = reinterpret_cast<const ulonglong2*>(sA + (jq * 4 + r) * 64);
            u64 accA = 0ULL, accB = 0ULL;
#pragma unroll
            for (int p = 0; p < 16; p++) {
                ulonglong2 q = wp[p];
                accA = fma2(q.x, x2[2 * p], accA);
                accB = fma2(q.y, x2[2 * p + 1], accB);
            }
            float a0, a1, b0, b1; unpack2(accA, a0, a1); unpack2(accB, b0, b1);
            h[r] = fmaxf((a0 + a1) + (b0 + b1), 0.f);
        }
#pragma unroll
        for (int r = 0; r < 4; r++) {
            u64 hh = dup2(h[r]);
            const ulonglong2* bp = reinterpret_cast<const ulonglong2*>(sBT + (jq * 4 + r) * 64);
#pragma unroll
            for (int p = 0; p < 16; p++) {
                ulonglong2 q = bp[p];
                y2[2 * p]     = fma2(q.x, hh, y2[2 * p]);
                y2[2 * p + 1] = fma2(q.y, hh, y2[2 * p + 1]);
            }
        }
    }
    ulonglong2* yp = reinterpret_cast<ulonglong2*>(g_y + (size_t)node * D);
#pragma unroll
    for (int q = 0; q < 16; q++) { ulonglong2 v; v.x = y2[2 * q]; v.y = y2[2 * q + 1]; yp[q] = v; }
}

// ---------------------------------------------------------------------------
// Scatter-add (unchanged, known-good): 64 threads per edge, scalar REDG.
// edge_index is INT32 (jax silently downcasts int64).
// ---------------------------------------------------------------------------
__global__ void scatter_kernel(const int* __restrict__ ei, int E, int n) {
    long long t = (long long)blockIdx.x * blockDim.x + threadIdx.x;
    int e = (int)(t >> 6);
    if (e >= E) return;
    int c = (int)(t & 63);
    int row = ei[e];
    int col = ei[E + e];
    if ((unsigned)row >= (unsigned)n || (unsigned)col >= (unsigned)n) return;
    float v = g_y[(size_t)row * D + c];
    atomicAdd(g_agg + (size_t)col * D + c, v);
    if (c == 0) atomicAdd(g_cnt + col, 1);
}

// ---------------------------------------------------------------------------
// Fused epilogue per node (packed):
//   a2 = LN1(agg/cnt); f2 = LN2(x + (x-a2)*w)
//   per output quad j: h = relu( W2a[j][0:64]·f2 + W2a[j][64:128]·a2 )
//                      o2 += W2b^T[j] * h    (rank-1, packed accumulators)
// No intermediate smem scratch.
// ---------------------------------------------------------------------------
__global__ __launch_bounds__(128) void epilogue_kernel(
    const float* __restrict__ x,
    const float* __restrict__ g1, const float* __restrict__ b1,
    const float* __restrict__ wrep,
    const float* __restrict__ g2, const float* __restrict__ b2,
    const float* __restrict__ W2a, const float* __restrict__ W2b,
    float* __restrict__ out, int n)
{
    extern __shared__ __align__(16) float smem[];
    float* sA  = smem;           // W2a [64][128] row-major (8192)
    float* sBT = smem + 8192;    // W2b^T [k][o]            (4096)
    float* sP  = smem + 12288;   // g1,b1,w,g2,b2           (320)
    int tid = threadIdx.x;
    for (int i = tid; i < 8192; i += 128) sA[i] = W2a[i];
    for (int i = tid; i < 4096; i += 128) { int o = i >> 6, k = i & 63; sBT[k * 64 + o] = W2b[i]; }
    if (tid < 64) {
        sP[tid] = g1[tid]; sP[64 + tid] = b1[tid]; sP[128 + tid] = wrep[tid];
        sP[192 + tid] = g2[tid]; sP[256 + tid] = b2[tid];
    }
    __syncthreads();

    int node = blockIdx.x * 128 + tid;
    if (node >= n) return;

    const u64* pg1 = reinterpret_cast<const u64*>(sP);
    const u64* pb1 = reinterpret_cast<const u64*>(sP + 64);
    const u64* pw  = reinterpret_cast<const u64*>(sP + 128);
    const u64* pg2 = reinterpret_cast<const u64*>(sP + 192);
    const u64* pb2 = reinterpret_cast<const u64*>(sP + 256);

    // a2 = agg / max(cnt,1), then LN1
    u64 a2[32];
    float inv = 1.0f / fmaxf((float)g_cnt[node], 1.0f);
    u64 inv2 = dup2(inv);
    const ulonglong2* sp = reinterpret_cast<const ulonglong2*>(g_agg + (size_t)node * D);
#pragma unroll
    for (int q = 0; q < 16; q++) {
        ulonglong2 v = sp[q];
        a2[2 * q] = mul2(v.x, inv2); a2[2 * q + 1] = mul2(v.y, inv2);
    }
    layernorm_packed(a2, pg1, pb1);

    // f2 = LN2( x + (x - a2) * w )
    u64 f2[32];
    const ulonglong2* xp = reinterpret_cast<const ulonglong2*>(x + (size_t)node * D);
#pragma unroll
    for (int q = 0; q < 16; q++) {
        ulonglong2 v = xp[q];
        u64 d0 = add2(v.x, neg2(a2[2 * q]));
        u64 d1 = add2(v.y, neg2(a2[2 * q + 1]));
        f2[2 * q]     = fma2(d0, pw[2 * q], v.x);
        f2[2 * q + 1] = fma2(d1, pw[2 * q + 1], v.y);
    }
    layernorm_packed(f2, pg2, pb2);

    // fused concat-GEMV + relu + output rank-1 accumulation
    u64 o2[32];
#pragma unroll
    for (int i = 0; i < 32; i++) o2[i] = 0ULL;

    for (int jq = 0; jq < 16; jq++) {
        float h[4];
#pragma unroll
        for (int r = 0; r < 4; r++) {
            const ulonglong2* wp = reinterpret_cast<const ulonglong2*>(sA + (jq * 4 + r) * 128);
            u64 accA = 0ULL, accB = 0ULL;
#pragma unroll
            for (int p = 0; p < 16; p++) {               // left half · f2
                ulonglong2 q = wp[p];
                accA = fma2(q.x, f2[2 * p], accA);
                accB = fma2(q.y, f2[2 * p + 1], accB);
            }
#pragma unroll
            for (int p = 0; p < 16; p++) {               // right half · a2
                ulonglong2 q = wp[16 + p];
                accA = fma2(q.x, a2[2 * p], accA);
                accB = fma2(q.y, a2[2 * p + 1], accB);
            }
            float a0, a1, b0, b1; unpack2(accA, a0, a1); unpack2(accB, b0, b1);
            h[r] = fmaxf((a0 + a1) + (b0 + b1), 0.f);
        }
#pragma unroll
        for (int r = 0; r < 4; r++) {
            u64 hh = dup2(h[r]);
            const ulonglong2* bp = reinterpret_cast<const ulonglong2*>(sBT + (jq * 4 + r) * 64);
#pragma unroll
            for (int p = 0; p < 16; p++) {
                ulonglong2 q = bp[p];
                o2[2 * p]     = fma2(q.x, hh, o2[2 * p]);
                o2[2 * p + 1] = fma2(q.y, hh, o2[2 * p + 1]);
            }
        }
    }
    ulonglong2* op = reinterpret_cast<ulonglong2*>(out + (size_t)node * D);
#pragma unroll
    for (int q = 0; q < 16; q++) { ulonglong2 v; v.x = o2[2 * q]; v.y = o2[2 * q + 1]; op[q] = v; }
}

// ---------------------------------------------------------------------------
// Launch
// ---------------------------------------------------------------------------
extern "C" void kernel_launch(void* const* d_in, const int* in_sizes, int n_in,
                              void* d_out, int out_size) {
    const float* x   = (const float*)d_in[0];
    const int*   ei  = (const int*)d_in[1];      // int32 (jax downcasts int64)
    const float* W1a = (const float*)d_in[2];
    const float* W1b = (const float*)d_in[3];
    const float* g1  = (const float*)d_in[4];
    const float* b1  = (const float*)d_in[5];
    const float* w   = (const float*)d_in[6];
    const float* g2  = (const float*)d_in[7];
    const float* b2  = (const float*)d_in[8];
    const float* W2a = (const float*)d_in[9];
    const float* W2b = (const float*)d_in[10];
    float* out = (float*)d_out;

    int n = in_sizes[0] / D;
    int E = in_sizes[1] / 2;

    const int EPI_SMEM = (8192 + 4096 + 320) * 4;   // 50432 B
    cudaFuncSetAttribute(epilogue_kernel, cudaFuncAttributeMaxDynamicSharedMemorySize, EPI_SMEM);

    zero_kernel<<<(n * 16 + 255) / 256, 256>>>(n);
    mlp1_kernel<<<(n + 127) / 128, 128>>>(x, W1a, W1b, n);
    {
        long long total = (long long)E * 64;
        int blocks = (int)((total + 255) / 256);
        scatter_kernel<<<blocks, 256>>>(ei, E, n);
    }
    epilogue_kernel<<<(n + 127) / 128, 128, EPI_SMEM>>>(x, g1, b1, w, g2, b2, W2a, W2b, out, n);
}

// round 5
// speedup vs baseline: 1.4765x; 1.3857x over previous
#include <cuda_runtime.h>

#define D 64
#define NMAX 50000
#define EMAX 800000

typedef unsigned long long u64;

// Scratch (device globals — no allocation allowed). 16B-aligned for v128 access.
__device__ __align__(16) float g_y[NMAX * D];     // per-node MLP1 output
__device__ __align__(16) float g_agg[NMAX * D];   // scatter accumulator
__device__ int g_cnt[NMAX];

// ---------------------------------------------------------------------------
// Packed fp32x2 helpers (sm_100+ PTX; FFMA2 is unreachable from plain C++)
// ---------------------------------------------------------------------------
__device__ __forceinline__ u64 pack2(float lo, float hi) {
    u64 r; asm("mov.b64 %0, {%1, %2};" : "=l"(r) : "f"(lo), "f"(hi)); return r;
}
__device__ __forceinline__ u64 dup2(float s) { return pack2(s, s); }
__device__ __forceinline__ void unpack2(u64 v, float& lo, float& hi) {
    asm("mov.b64 {%0, %1}, %2;" : "=f"(lo), "=f"(hi) : "l"(v));
}
__device__ __forceinline__ u64 fma2(u64 a, u64 b, u64 c) {
    u64 d; asm("fma.rn.f32x2 %0, %1, %2, %3;" : "=l"(d) : "l"(a), "l"(b), "l"(c)); return d;
}
__device__ __forceinline__ u64 add2(u64 a, u64 b) {
    u64 d; asm("add.rn.f32x2 %0, %1, %2;" : "=l"(d) : "l"(a), "l"(b)); return d;
}
__device__ __forceinline__ u64 mul2(u64 a, u64 b) {
    u64 d; asm("mul.rn.f32x2 %0, %1, %2;" : "=l"(d) : "l"(a), "l"(b)); return d;
}
__device__ __forceinline__ u64 neg2(u64 a) { return a ^ 0x8000000080000000ULL; }

// Packed LayerNorm over 32 pairs (64 features), biased var, eps=1e-5.
__device__ __forceinline__ void layernorm_packed(u64* v, const u64* __restrict__ pg,
                                                 const u64* __restrict__ pb) {
    u64 s = 0ULL;
#pragma unroll
    for (int i = 0; i < 32; i++) s = add2(s, v[i]);
    float lo, hi; unpack2(s, lo, hi);
    float m = (lo + hi) * (1.f / 64.f);
    u64 mneg = dup2(-m);
    u64 acc = 0ULL;
#pragma unroll
    for (int i = 0; i < 32; i++) { u64 d = add2(v[i], mneg); acc = fma2(d, d, acc); }
    unpack2(acc, lo, hi);
    float r = rsqrtf((lo + hi) * (1.f / 64.f) + 1e-5f);
    u64 r2 = dup2(r);
#pragma unroll
    for (int i = 0; i < 32; i++) {
        u64 d = mul2(add2(v[i], mneg), r2);
        v[i] = fma2(d, pg[i], pb[i]);
    }
}

// ---------------------------------------------------------------------------
// Zero the scatter accumulators
// ---------------------------------------------------------------------------
__global__ void zero_kernel(int n) {
    int i = blockIdx.x * blockDim.x + threadIdx.x;
    if (i < n * (D / 4)) reinterpret_cast<float4*>(g_agg)[i] = make_float4(0.f, 0.f, 0.f, 0.f);
    if (i < n) g_cnt[i] = 0;
}

// ---------------------------------------------------------------------------
// MLP1 per node: y = relu(x @ W1a^T) @ W1b^T  (moved before gather: 16x FLOP cut)
// ---------------------------------------------------------------------------
__global__ __launch_bounds__(128) void mlp1_kernel(
    const float* __restrict__ x, const float* __restrict__ W1a,
    const float* __restrict__ W1b, int n)
{
    __shared__ __align__(16) float sA[4096];   // W1a row-major
    __shared__ __align__(16) float sBT[4096];  // W1b^T: sBT[k*64+o] = W1b[o][k]
    int tid = threadIdx.x;
    for (int i = tid; i < 4096; i += 128) {
        sA[i] = W1a[i];
        int o = i >> 6, k = i & 63;
        sBT[k * 64 + o] = W1b[i];
    }
    __syncthreads();

    int node = blockIdx.x * 128 + tid;
    if (node >= n) return;

    u64 x2[32];
    const ulonglong2* xp = reinterpret_cast<const ulonglong2*>(x + (size_t)node * D);
#pragma unroll
    for (int q = 0; q < 16; q++) { ulonglong2 v = xp[q]; x2[2 * q] = v.x; x2[2 * q + 1] = v.y; }

    u64 y2[32];
#pragma unroll
    for (int i = 0; i < 32; i++) y2[i] = 0ULL;

    for (int jq = 0; jq < 16; jq++) {
        float h[4];
#pragma unroll
        for (int r = 0; r < 4; r++) {
            const ulonglong2* wp = reinterpret_cast<const ulonglong2*>(sA + (jq * 4 + r) * 64);
            u64 accA = 0ULL, accB = 0ULL;
#pragma unroll
            for (int p = 0; p < 16; p++) {
                ulonglong2 q = wp[p];
                accA = fma2(q.x, x2[2 * p], accA);
                accB = fma2(q.y, x2[2 * p + 1], accB);
            }
            float a0, a1, b0, b1; unpack2(accA, a0, a1); unpack2(accB, b0, b1);
            h[r] = fmaxf((a0 + a1) + (b0 + b1), 0.f);
        }
#pragma unroll
        for (int r = 0; r < 4; r++) {
            u64 hh = dup2(h[r]);
            const ulonglong2* bp = reinterpret_cast<const ulonglong2*>(sBT + (jq * 4 + r) * 64);
#pragma unroll
            for (int p = 0; p < 16; p++) {
                ulonglong2 q = bp[p];
                y2[2 * p]     = fma2(q.x, hh, y2[2 * p]);
                y2[2 * p + 1] = fma2(q.y, hh, y2[2 * p + 1]);
            }
        }
    }
    ulonglong2* yp = reinterpret_cast<ulonglong2*>(g_y + (size_t)node * D);
#pragma unroll
    for (int q = 0; q < 16; q++) { ulonglong2 v; v.x = y2[2 * q]; v.y = y2[2 * q + 1]; yp[q] = v; }
}

// ---------------------------------------------------------------------------
// Scatter-add: 16 threads per edge, one float4 per thread, native vector
// atomic (sm_90+): RED.ADD 16B ops. 4x fewer L2-atomic ops than scalar,
// 4x fewer index loads. edge_index is INT32 (jax downcasts int64).
// ---------------------------------------------------------------------------
__global__ void scatter_kernel(const int* __restrict__ ei, int E, int n) {
    long long t = (long long)blockIdx.x * blockDim.x + threadIdx.x;
    int e = (int)(t >> 4);
    if (e >= E) return;
    int c = (int)(t & 15);
    int row = ei[e];
    int col = ei[E + e];
    if ((unsigned)row >= (unsigned)n || (unsigned)col >= (unsigned)n) return;
    float4 v = reinterpret_cast<const float4*>(g_y + (size_t)row * D)[c];
    atomicAdd(reinterpret_cast<float4*>(g_agg + (size_t)col * D) + c, v);
    if (c == 0) atomicAdd(g_cnt + col, 1);
}

// ---------------------------------------------------------------------------
// Fused epilogue per node (packed):
//   a2 = LN1(agg/cnt); f2 = LN2(x + (x-a2)*w)
//   per output quad j: h = relu( W2a[j][0:64]·f2 + W2a[j][64:128]·a2 )
//                      o2 += W2b^T[j] * h    (rank-1, packed accumulators)
// ---------------------------------------------------------------------------
__global__ __launch_bounds__(128) void epilogue_kernel(
    const float* __restrict__ x,
    const float* __restrict__ g1, const float* __restrict__ b1,
    const float* __restrict__ wrep,
    const float* __restrict__ g2, const float* __restrict__ b2,
    const float* __restrict__ W2a, const float* __restrict__ W2b,
    float* __restrict__ out, int n)
{
    extern __shared__ __align__(16) float smem[];
    float* sA  = smem;           // W2a [64][128] row-major (8192)
    float* sBT = smem + 8192;    // W2b^T [k][o]            (4096)
    float* sP  = smem + 12288;   // g1,b1,w,g2,b2           (320)
    int tid = threadIdx.x;
    for (int i = tid; i < 8192; i += 128) sA[i] = W2a[i];
    for (int i = tid; i < 4096; i += 128) { int o = i >> 6, k = i & 63; sBT[k * 64 + o] = W2b[i]; }
    if (tid < 64) {
        sP[tid] = g1[tid]; sP[64 + tid] = b1[tid]; sP[128 + tid] = wrep[tid];
        sP[192 + tid] = g2[tid]; sP[256 + tid] = b2[tid];
    }
    __syncthreads();

    int node = blockIdx.x * 128 + tid;
    if (node >= n) return;

    const u64* pg1 = reinterpret_cast<const u64*>(sP);
    const u64* pb1 = reinterpret_cast<const u64*>(sP + 64);
    const u64* pw  = reinterpret_cast<const u64*>(sP + 128);
    const u64* pg2 = reinterpret_cast<const u64*>(sP + 192);
    const u64* pb2 = reinterpret_cast<const u64*>(sP + 256);

    // a2 = agg / max(cnt,1), then LN1
    u64 a2[32];
    float inv = 1.0f / fmaxf((float)g_cnt[node], 1.0f);
    u64 inv2 = dup2(inv);
    const ulonglong2* sp = reinterpret_cast<const ulonglong2*>(g_agg + (size_t)node * D);
#pragma unroll
    for (int q = 0; q < 16; q++) {
        ulonglong2 v = sp[q];
        a2[2 * q] = mul2(v.x, inv2); a2[2 * q + 1] = mul2(v.y, inv2);
    }
    layernorm_packed(a2, pg1, pb1);

    // f2 = LN2( x + (x - a2) * w )
    u64 f2[32];
    const ulonglong2* xp = reinterpret_cast<const ulonglong2*>(x + (size_t)node * D);
#pragma unroll
    for (int q = 0; q < 16; q++) {
        ulonglong2 v = xp[q];
        u64 d0 = add2(v.x, neg2(a2[2 * q]));
        u64 d1 = add2(v.y, neg2(a2[2 * q + 1]));
        f2[2 * q]     = fma2(d0, pw[2 * q], v.x);
        f2[2 * q + 1] = fma2(d1, pw[2 * q + 1], v.y);
    }
    layernorm_packed(f2, pg2, pb2);

    // fused concat-GEMV + relu + output rank-1 accumulation
    u64 o2[32];
#pragma unroll
    for (int i = 0; i < 32; i++) o2[i] = 0ULL;

    for (int jq = 0; jq < 16; jq++) {
        float h[4];
#pragma unroll
        for (int r = 0; r < 4; r++) {
            const ulonglong2* wp = reinterpret_cast<const ulonglong2*>(sA + (jq * 4 + r) * 128);
            u64 accA = 0ULL, accB = 0ULL;
#pragma unroll
            for (int p = 0; p < 16; p++) {               // left half · f2
                ulonglong2 q = wp[p];
                accA = fma2(q.x, f2[2 * p], accA);
                accB = fma2(q.y, f2[2 * p + 1], accB);
            }
#pragma unroll
            for (int p = 0; p < 16; p++) {               // right half · a2
                ulonglong2 q = wp[16 + p];
                accA = fma2(q.x, a2[2 * p], accA);
                accB = fma2(q.y, a2[2 * p + 1], accB);
            }
            float a0, a1, b0, b1; unpack2(accA, a0, a1); unpack2(accB, b0, b1);
            h[r] = fmaxf((a0 + a1) + (b0 + b1), 0.f);
        }
#pragma unroll
        for (int r = 0; r < 4; r++) {
            u64 hh = dup2(h[r]);
            const ulonglong2* bp = reinterpret_cast<const ulonglong2*>(sBT + (jq * 4 + r) * 64);
#pragma unroll
            for (int p = 0; p < 16; p++) {
                ulonglong2 q = bp[p];
                o2[2 * p]     = fma2(q.x, hh, o2[2 * p]);
                o2[2 * p + 1] = fma2(q.y, hh, o2[2 * p + 1]);
            }
        }
    }
    ulonglong2* op = reinterpret_cast<ulonglong2*>(out + (size_t)node * D);
#pragma unroll
    for (int q = 0; q < 16; q++) { ulonglong2 v; v.x = o2[2 * q]; v.y = o2[2 * q + 1]; op[q] = v; }
}

// ---------------------------------------------------------------------------
// Launch
// ---------------------------------------------------------------------------
extern "C" void kernel_launch(void* const* d_in, const int* in_sizes, int n_in,
                              void* d_out, int out_size) {
    const float* x   = (const float*)d_in[0];
    const int*   ei  = (const int*)d_in[1];      // int32 (jax downcasts int64)
    const float* W1a = (const float*)d_in[2];
    const float* W1b = (const float*)d_in[3];
    const float* g1  = (const float*)d_in[4];
    const float* b1  = (const float*)d_in[5];
    const float* w   = (const float*)d_in[6];
    const float* g2  = (const float*)d_in[7];
    const float* b2  = (const float*)d_in[8];
    const float* W2a = (const float*)d_in[9];
    const float* W2b = (const float*)d_in[10];
    float* out = (float*)d_out;

    int n = in_sizes[0] / D;
    int E = in_sizes[1] / 2;

    const int EPI_SMEM = (8192 + 4096 + 320) * 4;   // 50432 B
    cudaFuncSetAttribute(epilogue_kernel, cudaFuncAttributeMaxDynamicSharedMemorySize, EPI_SMEM);

    zero_kernel<<<(n * 16 + 255) / 256, 256>>>(n);
    mlp1_kernel<<<(n + 127) / 128, 128>>>(x, W1a, W1b, n);
    {
        long long total = (long long)E * 16;
        int blocks = (int)((total + 255) / 256);
        scatter_kernel<<<blocks, 256>>>(ei, E, n);
    }
    epilogue_kernel<<<(n + 127) / 128, 128, EPI_SMEM>>>(x, g1, b1, w, g2, b2, W2a, W2b, out, n);
}

// round 6
// speedup vs baseline: 1.8469x; 1.2509x over previous
#include <cuda_runtime.h>

#define D 64
#define NMAX 50000
#define EMAX 800000

typedef unsigned long long u64;

// Scratch (device globals — no allocation allowed). 16B-aligned.
__device__ __align__(16) float g_y[NMAX * D];     // per-node MLP1 output
__device__ __align__(16) float g_agg[NMAX * D];   // scatter accumulator
__device__ int g_cnt[NMAX];

// ---------------------------------------------------------------------------
// Packed fp32x2 helpers (sm_100+; FFMA2 unreachable from plain C++)
// ---------------------------------------------------------------------------
__device__ __forceinline__ u64 pack2(float lo, float hi) {
    u64 r; asm("mov.b64 %0, {%1, %2};" : "=l"(r) : "f"(lo), "f"(hi)); return r;
}
__device__ __forceinline__ u64 dup2(float s) { return pack2(s, s); }
__device__ __forceinline__ void unpack2(u64 v, float& lo, float& hi) {
    asm("mov.b64 {%0, %1}, %2;" : "=f"(lo), "=f"(hi) : "l"(v));
}
__device__ __forceinline__ u64 fma2(u64 a, u64 b, u64 c) {
    u64 d; asm("fma.rn.f32x2 %0, %1, %2, %3;" : "=l"(d) : "l"(a), "l"(b), "l"(c)); return d;
}
__device__ __forceinline__ u64 add2(u64 a, u64 b) {
    u64 d; asm("add.rn.f32x2 %0, %1, %2;" : "=l"(d) : "l"(a), "l"(b)); return d;
}
__device__ __forceinline__ u64 mul2(u64 a, u64 b) {
    u64 d; asm("mul.rn.f32x2 %0, %1, %2;" : "=l"(d) : "l"(a), "l"(b)); return d;
}
__device__ __forceinline__ u64 neg2(u64 a) { return a ^ 0x8000000080000000ULL; }

// Packed LayerNorm over 32 pairs (64 features), biased var, eps=1e-5.
__device__ __forceinline__ void layernorm_packed(u64* v, const u64* __restrict__ pg,
                                                 const u64* __restrict__ pb) {
    u64 s = 0ULL;
#pragma unroll
    for (int i = 0; i < 32; i++) s = add2(s, v[i]);
    float lo, hi; unpack2(s, lo, hi);
    float m = (lo + hi) * (1.f / 64.f);
    u64 mneg = dup2(-m);
    u64 acc = 0ULL;
#pragma unroll
    for (int i = 0; i < 32; i++) { u64 d = add2(v[i], mneg); acc = fma2(d, d, acc); }
    unpack2(acc, lo, hi);
    float r = rsqrtf((lo + hi) * (1.f / 64.f) + 1e-5f);
    u64 r2 = dup2(r);
#pragma unroll
    for (int i = 0; i < 32; i++) {
        u64 d = mul2(add2(v[i], mneg), r2);
        v[i] = fma2(d, pg[i], pb[i]);
    }
}

// ---------------------------------------------------------------------------
// Register-tiled GEMM core: block tile = 128 nodes x 64 outputs.
// Thread (ng = tid&15, og = tid>>4) computes nodes [ng*8, +8) x outs [og*8, +8).
// sC: k-major activations [K][132]; sW: k-major weights [K][68] (sW[k][j] = W[j][k]).
// acc[op][nn] u64 = (out[j0+2op], out[j0+2op+1]) for node ng*8+nn.
// Per k: 4 LDS.128 + 8 dup-mov + 32 fma2.
// ---------------------------------------------------------------------------
#define CPITCH 132
#define WPITCH 68

template <int K>
__device__ __forceinline__ void gemm_tile(const float* __restrict__ sC,
                                          const float* __restrict__ sW,
                                          int ng, int og, u64 acc[4][8]) {
#pragma unroll
    for (int op = 0; op < 4; op++)
#pragma unroll
        for (int nn = 0; nn < 8; nn++) acc[op][nn] = 0ULL;

    const float* cr = sC + ng * 8;
    const float* wr = sW + og * 8;
#pragma unroll 4
    for (int k = 0; k < K; k++) {
        float4 ca = *reinterpret_cast<const float4*>(cr + k * CPITCH);
        float4 cb = *reinterpret_cast<const float4*>(cr + k * CPITCH + 4);
        ulonglong2 w01 = *reinterpret_cast<const ulonglong2*>(wr + k * WPITCH);
        ulonglong2 w23 = *reinterpret_cast<const ulonglong2*>(wr + k * WPITCH + 4);
        u64 wp0 = w01.x, wp1 = w01.y, wp2 = w23.x, wp3 = w23.y;
        float cv[8] = {ca.x, ca.y, ca.z, ca.w, cb.x, cb.y, cb.z, cb.w};
#pragma unroll
        for (int nn = 0; nn < 8; nn++) {
            u64 cd = dup2(cv[nn]);
            acc[0][nn] = fma2(wp0, cd, acc[0][nn]);
            acc[1][nn] = fma2(wp1, cd, acc[1][nn]);
            acc[2][nn] = fma2(wp2, cd, acc[2][nn]);
            acc[3][nn] = fma2(wp3, cd, acc[3][nn]);
        }
    }
}

// Stage activations [node][K] (global, row-major) -> sC[k][node], zero OOR nodes.
template <int K>
__device__ __forceinline__ void stage_C(const float* __restrict__ g, int base, int n,
                                        float* __restrict__ sC, int tid) {
    const int K4 = K / 4;
    for (int idx = tid; idx < 128 * K4; idx += 128) {
        int node = idx / K4, k4 = idx % K4;
        float4 v = make_float4(0.f, 0.f, 0.f, 0.f);
        if (base + node < n) v = reinterpret_cast<const float4*>(g + (size_t)(base + node) * K)[k4];
        sC[(4 * k4 + 0) * CPITCH + node] = v.x;
        sC[(4 * k4 + 1) * CPITCH + node] = v.y;
        sC[(4 * k4 + 2) * CPITCH + node] = v.z;
        sC[(4 * k4 + 3) * CPITCH + node] = v.w;
    }
}

// Stage weights W[64][K] (global, row-major) -> sW[k][j].
template <int K>
__device__ __forceinline__ void stage_W(const float* __restrict__ w,
                                        float* __restrict__ sW, int tid) {
    const int K4 = K / 4;
    for (int idx = tid; idx < 64 * K4; idx += 128) {
        int j = idx / K4, k4 = idx % K4;
        float4 v = reinterpret_cast<const float4*>(w + j * K)[k4];
        sW[(4 * k4 + 0) * WPITCH + j] = v.x;
        sW[(4 * k4 + 1) * WPITCH + j] = v.y;
        sW[(4 * k4 + 2) * WPITCH + j] = v.z;
        sW[(4 * k4 + 3) * WPITCH + j] = v.w;
    }
}

// ReLU acc and write as hidden tile sH[j][node] (k-major for the next GEMM).
__device__ __forceinline__ void relu_to_smem(u64 acc[4][8], float* __restrict__ sH,
                                             int ng, int og) {
#pragma unroll
    for (int op = 0; op < 4; op++)
#pragma unroll
        for (int nn = 0; nn < 8; nn++) {
            float lo, hi; unpack2(acc[op][nn], lo, hi);
            sH[(og * 8 + 2 * op) * CPITCH + ng * 8 + nn]     = fmaxf(lo, 0.f);
            sH[(og * 8 + 2 * op + 1) * CPITCH + ng * 8 + nn] = fmaxf(hi, 0.f);
        }
}

// Store acc tile to global out[node][j], guarded by node < n.
__device__ __forceinline__ void store_out(u64 acc[4][8], float* __restrict__ out,
                                          int base, int n, int ng, int og) {
#pragma unroll
    for (int nn = 0; nn < 8; nn++) {
        int node = base + ng * 8 + nn;
        if (node < n) {
            ulonglong2* p = reinterpret_cast<ulonglong2*>(out + (size_t)node * D + og * 8);
            ulonglong2 v0; v0.x = acc[0][nn]; v0.y = acc[1][nn];
            ulonglong2 v1; v1.x = acc[2][nn]; v1.y = acc[3][nn];
            p[0] = v0; p[1] = v1;
        }
    }
}

// ---------------------------------------------------------------------------
// Zero the scatter accumulators
// ---------------------------------------------------------------------------
__global__ void zero_kernel(int n) {
    int i = blockIdx.x * blockDim.x + threadIdx.x;
    if (i < n * (D / 4)) reinterpret_cast<float4*>(g_agg)[i] = make_float4(0.f, 0.f, 0.f, 0.f);
    if (i < n) g_cnt[i] = 0;
}

// ---------------------------------------------------------------------------
// MLP1: y = relu(x @ W1a^T) @ W1b^T  (per-node; 16x FLOP cut vs per-edge)
// Fused two GEMMs; hidden tile stays in smem (overwrites sC).
// smem: sC 64*132 + sW 64*68 = 12800 floats = 51200 B
// ---------------------------------------------------------------------------
__global__ __launch_bounds__(128) void mlp1_kernel(
    const float* __restrict__ x, const float* __restrict__ W1a,
    const float* __restrict__ W1b, int n)
{
    extern __shared__ __align__(16) float smem[];
    float* sC = smem;                  // [64][132]
    float* sW = smem + 64 * CPITCH;    // [64][68]
    int tid = threadIdx.x;
    int base = blockIdx.x * 128;
    int ng = tid & 15, og = tid >> 4;

    stage_C<64>(x, base, n, sC, tid);
    stage_W<64>(W1a, sW, tid);
    __syncthreads();

    u64 acc[4][8];
    gemm_tile<64>(sC, sW, ng, og, acc);
    __syncthreads();                   // all reads of sC/sW done

    relu_to_smem(acc, sC, ng, og);     // sC becomes hidden tile h[j][node]
    stage_W<64>(W1b, sW, tid);
    __syncthreads();

    gemm_tile<64>(sC, sW, ng, og, acc);
    store_out(acc, g_y, base, n, ng, og);
}

// ---------------------------------------------------------------------------
// Scatter-add: 16 threads/edge, float4 vector atomics (sm_90+).
// edge_index is INT32 (jax silently downcasts int64).
// ---------------------------------------------------------------------------
__global__ void scatter_kernel(const int* __restrict__ ei, int E, int n) {
    long long t = (long long)blockIdx.x * blockDim.x + threadIdx.x;
    int e = (int)(t >> 4);
    if (e >= E) return;
    int c = (int)(t & 15);
    int row = ei[e];
    int col = ei[E + e];
    if ((unsigned)row >= (unsigned)n || (unsigned)col >= (unsigned)n) return;
    float4 v = reinterpret_cast<const float4*>(g_y + (size_t)row * D)[c];
    atomicAdd(reinterpret_cast<float4*>(g_agg + (size_t)col * D) + c, v);
    if (c == 0) atomicAdd(g_cnt + col, 1);
}

// ---------------------------------------------------------------------------
// Fused epilogue:
//  Phase LN (thread = node): a = LN1(agg/cnt); fx = LN2(x + (x-a)*w);
//    write concat [fx; a] k-major into sC[k][node] (k = 0..127).
//  GEMM h = relu(C @ W2a^T)  -> sH (reuses sC rows 0..63)
//  GEMM out = h @ W2b^T      -> global
// smem: sC 128*132 + sW 128*68 = 25600 floats = 102400 B
// ---------------------------------------------------------------------------
__global__ __launch_bounds__(128) void epilogue_kernel(
    const float* __restrict__ x,
    const float* __restrict__ g1, const float* __restrict__ b1,
    const float* __restrict__ wrep,
    const float* __restrict__ g2, const float* __restrict__ b2,
    const float* __restrict__ W2a, const float* __restrict__ W2b,
    float* __restrict__ out, int n)
{
    extern __shared__ __align__(16) float smem[];
    float* sC = smem;                   // [128][132]
    float* sW = smem + 128 * CPITCH;    // [128][68]
    int tid = threadIdx.x;
    int base = blockIdx.x * 128;
    int ng = tid & 15, og = tid >> 4;
    int node = base + tid;

    stage_W<128>(W2a, sW, tid);

    // ---- LN phase (packed, per-thread node) ----
    {
        const u64* pg1 = reinterpret_cast<const u64*>(g1);
        const u64* pb1 = reinterpret_cast<const u64*>(b1);
        const u64* pw  = reinterpret_cast<const u64*>(wrep);
        const u64* pg2 = reinterpret_cast<const u64*>(g2);
        const u64* pb2 = reinterpret_cast<const u64*>(b2);

        u64 a2[32], f2[32];
        bool valid = node < n;
        float inv = valid ? 1.0f / fmaxf((float)g_cnt[node], 1.0f) : 0.f;
        u64 inv2 = dup2(inv);
        const ulonglong2* sp = reinterpret_cast<const ulonglong2*>(g_agg + (size_t)(valid ? node : 0) * D);
        const ulonglong2* xp = reinterpret_cast<const ulonglong2*>(x + (size_t)(valid ? node : 0) * D);
#pragma unroll
        for (int q = 0; q < 16; q++) {
            ulonglong2 v = sp[q];
            a2[2 * q] = mul2(v.x, inv2); a2[2 * q + 1] = mul2(v.y, inv2);
        }
        layernorm_packed(a2, pg1, pb1);
#pragma unroll
        for (int q = 0; q < 16; q++) {
            ulonglong2 v = xp[q];
            u64 vx = valid ? v.x : 0ULL, vy = valid ? v.y : 0ULL;
            u64 d0 = add2(vx, neg2(a2[2 * q]));
            u64 d1 = add2(vy, neg2(a2[2 * q + 1]));
            f2[2 * q]     = fma2(d0, pw[2 * q], vx);
            f2[2 * q + 1] = fma2(d1, pw[2 * q + 1], vy);
        }
        layernorm_packed(f2, pg2, pb2);

        // write concat tile k-major: rows 0..63 = fx, 64..127 = a
#pragma unroll
        for (int i = 0; i < 32; i++) {
            float lo, hi;
            unpack2(f2[i], lo, hi);
            sC[(2 * i) * CPITCH + tid] = lo; sC[(2 * i + 1) * CPITCH + tid] = hi;
            unpack2(a2[i], lo, hi);
            sC[(64 + 2 * i) * CPITCH + tid] = lo; sC[(64 + 2 * i + 1) * CPITCH + tid] = hi;
        }
    }
    __syncthreads();

    u64 acc[4][8];
    gemm_tile<128>(sC, sW, ng, og, acc);
    __syncthreads();

    relu_to_smem(acc, sC, ng, og);      // hidden tile in sC rows 0..63
    stage_W<64>(W2b, sW, tid);
    __syncthreads();

    gemm_tile<64>(sC, sW, ng, og, acc);
    store_out(acc, out, base, n, ng, og);
}

// ---------------------------------------------------------------------------
// Launch
// ---------------------------------------------------------------------------
extern "C" void kernel_launch(void* const* d_in, const int* in_sizes, int n_in,
                              void* d_out, int out_size) {
    const float* x   = (const float*)d_in[0];
    const int*   ei  = (const int*)d_in[1];      // int32 (jax downcasts int64)
    const float* W1a = (const float*)d_in[2];
    const float* W1b = (const float*)d_in[3];
    const float* g1  = (const float*)d_in[4];
    const float* b1  = (const float*)d_in[5];
    const float* w   = (const float*)d_in[6];
    const float* g2  = (const float*)d_in[7];
    const float* b2  = (const float*)d_in[8];
    const float* W2a = (const float*)d_in[9];
    const float* W2b = (const float*)d_in[10];
    float* out = (float*)d_out;

    int n = in_sizes[0] / D;
    int E = in_sizes[1] / 2;
    int blocks = (n + 127) / 128;

    const int MLP1_SMEM = (64 * CPITCH + 64 * WPITCH) * 4;     // 51200 B
    const int EPI_SMEM  = (128 * CPITCH + 128 * WPITCH) * 4;   // 102400 B
    cudaFuncSetAttribute(mlp1_kernel, cudaFuncAttributeMaxDynamicSharedMemorySize, MLP1_SMEM);
    cudaFuncSetAttribute(epilogue_kernel, cudaFuncAttributeMaxDynamicSharedMemorySize, EPI_SMEM);

    zero_kernel<<<(n * 16 + 255) / 256, 256>>>(n);
    mlp1_kernel<<<blocks, 128, MLP1_SMEM>>>(x, W1a, W1b, n);
    {
        long long total = (long long)E * 16;
        int sblocks = (int)((total + 255) / 256);
        scatter_kernel<<<sblocks, 256>>>(ei, E, n);
    }
    epilogue_kernel<<<blocks, 128, EPI_SMEM>>>(x, g1, b1, w, g2, b2, W2a, W2b, out, n);
}

// round 7
// speedup vs baseline: 1.9433x; 1.0522x over previous
#include <cuda_runtime.h>

#define D 64
#define NMAX 50000
#define EMAX 800000

typedef unsigned long long u64;

// Scratch (device globals — no allocation allowed). 16B-aligned.
__device__ __align__(16) float g_y[NMAX * D];     // per-node MLP1 output
__device__ __align__(16) float g_agg[NMAX * D];   // scatter accumulator
__device__ int g_cnt[NMAX];

// ---------------------------------------------------------------------------
// Packed fp32x2 helpers (sm_100+; FFMA2 unreachable from plain C++)
// ---------------------------------------------------------------------------
__device__ __forceinline__ u64 pack2(float lo, float hi) {
    u64 r; asm("mov.b64 %0, {%1, %2};" : "=l"(r) : "f"(lo), "f"(hi)); return r;
}
__device__ __forceinline__ u64 dup2(float s) { return pack2(s, s); }
__device__ __forceinline__ void unpack2(u64 v, float& lo, float& hi) {
    asm("mov.b64 {%0, %1}, %2;" : "=f"(lo), "=f"(hi) : "l"(v));
}
__device__ __forceinline__ u64 fma2(u64 a, u64 b, u64 c) {
    u64 d; asm("fma.rn.f32x2 %0, %1, %2, %3;" : "=l"(d) : "l"(a), "l"(b), "l"(c)); return d;
}
__device__ __forceinline__ u64 add2(u64 a, u64 b) {
    u64 d; asm("add.rn.f32x2 %0, %1, %2;" : "=l"(d) : "l"(a), "l"(b)); return d;
}
__device__ __forceinline__ u64 mul2(u64 a, u64 b) {
    u64 d; asm("mul.rn.f32x2 %0, %1, %2;" : "=l"(d) : "l"(a), "l"(b)); return d;
}
__device__ __forceinline__ u64 neg2(u64 a) { return a ^ 0x8000000080000000ULL; }
__device__ __forceinline__ float hsum2(u64 v) { float lo, hi; unpack2(v, lo, hi); return lo + hi; }

#define CPITCH 132
#define WPITCH 68
#define NT 256

// ---------------------------------------------------------------------------
// Register-tiled GEMM: block tile = 128 nodes x 64 outputs, 256 threads.
// Thread (ng = tid&31, og = tid>>5): nodes [ng*4,+4) x outputs [og*8,+8).
// og is warp-uniform -> W loads are pure broadcast LDS.128.
// acc[op][nn] = packed (out j0+2op, j0+2op+1) for node ng*4+nn.
// Per k: 1 C-LDS.128 + 2 W-LDS.128 + 4 dup + 16 fma2.
// ---------------------------------------------------------------------------
template <int K>
__device__ __forceinline__ void gemm_tile(const float* __restrict__ sC,
                                          const float* __restrict__ sW,
                                          int ng, int og, u64 acc[4][4]) {
#pragma unroll
    for (int op = 0; op < 4; op++)
#pragma unroll
        for (int nn = 0; nn < 4; nn++) acc[op][nn] = 0ULL;

    const float* cr = sC + ng * 4;
    const float* wr = sW + og * 8;
#pragma unroll 4
    for (int k = 0; k < K; k++) {
        float4 ca = *reinterpret_cast<const float4*>(cr + k * CPITCH);
        ulonglong2 w01 = *reinterpret_cast<const ulonglong2*>(wr + k * WPITCH);
        ulonglong2 w23 = *reinterpret_cast<const ulonglong2*>(wr + k * WPITCH + 4);
        float cv[4] = {ca.x, ca.y, ca.z, ca.w};
#pragma unroll
        for (int nn = 0; nn < 4; nn++) {
            u64 cd = dup2(cv[nn]);
            acc[0][nn] = fma2(w01.x, cd, acc[0][nn]);
            acc[1][nn] = fma2(w01.y, cd, acc[1][nn]);
            acc[2][nn] = fma2(w23.x, cd, acc[2][nn]);
            acc[3][nn] = fma2(w23.y, cd, acc[3][nn]);
        }
    }
}

// Stage activations [node][K] row-major -> sC[k][node], zero OOR nodes.
template <int K>
__device__ __forceinline__ void stage_C(const float* __restrict__ g, int base, int n,
                                        float* __restrict__ sC, int tid) {
    const int K4 = K / 4;
    for (int idx = tid; idx < 128 * K4; idx += NT) {
        int node = idx / K4, k4 = idx % K4;
        float4 v = make_float4(0.f, 0.f, 0.f, 0.f);
        if (base + node < n) v = reinterpret_cast<const float4*>(g + (size_t)(base + node) * K)[k4];
        sC[(4 * k4 + 0) * CPITCH + node] = v.x;
        sC[(4 * k4 + 1) * CPITCH + node] = v.y;
        sC[(4 * k4 + 2) * CPITCH + node] = v.z;
        sC[(4 * k4 + 3) * CPITCH + node] = v.w;
    }
}

// Stage weights W[64][K] row-major -> sW[k][j].
template <int K>
__device__ __forceinline__ void stage_W(const float* __restrict__ w,
                                        float* __restrict__ sW, int tid) {
    const int K4 = K / 4;
    for (int idx = tid; idx < 64 * K4; idx += NT) {
        int j = idx / K4, k4 = idx % K4;
        float4 v = reinterpret_cast<const float4*>(w + j * K)[k4];
        sW[(4 * k4 + 0) * WPITCH + j] = v.x;
        sW[(4 * k4 + 1) * WPITCH + j] = v.y;
        sW[(4 * k4 + 2) * WPITCH + j] = v.z;
        sW[(4 * k4 + 3) * WPITCH + j] = v.w;
    }
}

// ReLU acc and write hidden tile sH[j][node] (k-major), STS.128 conflict-free.
__device__ __forceinline__ void relu_to_smem(u64 acc[4][4], float* __restrict__ sH,
                                             int ng, int og) {
#pragma unroll
    for (int op = 0; op < 4; op++) {
        float4 vlo, vhi;
        float l0, h0, l1, h1, l2, h2, l3, h3;
        unpack2(acc[op][0], l0, h0); unpack2(acc[op][1], l1, h1);
        unpack2(acc[op][2], l2, h2); unpack2(acc[op][3], l3, h3);
        vlo = make_float4(fmaxf(l0, 0.f), fmaxf(l1, 0.f), fmaxf(l2, 0.f), fmaxf(l3, 0.f));
        vhi = make_float4(fmaxf(h0, 0.f), fmaxf(h1, 0.f), fmaxf(h2, 0.f), fmaxf(h3, 0.f));
        *reinterpret_cast<float4*>(sH + (og * 8 + 2 * op) * CPITCH + ng * 4) = vlo;
        *reinterpret_cast<float4*>(sH + (og * 8 + 2 * op + 1) * CPITCH + ng * 4) = vhi;
    }
}

// Store acc tile to out[node][og*8..+8), guarded.
__device__ __forceinline__ void store_out(u64 acc[4][4], float* __restrict__ out,
                                          int base, int n, int ng, int og) {
#pragma unroll
    for (int nn = 0; nn < 4; nn++) {
        int node = base + ng * 4 + nn;
        if (node < n) {
            ulonglong2* p = reinterpret_cast<ulonglong2*>(out + (size_t)node * D + og * 8);
            ulonglong2 v0; v0.x = acc[0][nn]; v0.y = acc[1][nn];
            ulonglong2 v1; v1.x = acc[2][nn]; v1.y = acc[3][nn];
            p[0] = v0; p[1] = v1;
        }
    }
}

// ---------------------------------------------------------------------------
// MLP1: y = relu(x @ W1a^T) @ W1b^T  (per-node; 16x FLOP cut vs per-edge).
// Also zeroes g_agg/g_cnt for this block's node range (runs before scatter).
// smem: 64*132 + 64*68 = 12800 floats = 51200 B
// ---------------------------------------------------------------------------
__global__ __launch_bounds__(NT, 2) void mlp1_kernel(
    const float* __restrict__ x, const float* __restrict__ W1a,
    const float* __restrict__ W1b, int n)
{
    extern __shared__ __align__(16) float smem[];
    float* sC = smem;                  // [64][132]
    float* sW = smem + 64 * CPITCH;    // [64][68]
    int tid = threadIdx.x;
    int base = blockIdx.x * 128;
    int ng = tid & 31, og = tid >> 5;

    stage_C<64>(x, base, n, sC, tid);
    stage_W<64>(W1a, sW, tid);
    // fold in zeroing of scatter accumulators for this node range
    {
        float4 z = make_float4(0.f, 0.f, 0.f, 0.f);
        for (int idx = tid; idx < 128 * 16; idx += NT) {
            int node = base + (idx >> 4);
            if (node < n) reinterpret_cast<float4*>(g_agg)[(size_t)node * 16 + (idx & 15)] = z;
        }
        if (tid < 128 && base + tid < n) g_cnt[base + tid] = 0;
    }
    __syncthreads();

    u64 acc[4][4];
    gemm_tile<64>(sC, sW, ng, og, acc);
    __syncthreads();

    relu_to_smem(acc, sC, ng, og);
    stage_W<64>(W1b, sW, tid);
    __syncthreads();

    gemm_tile<64>(sC, sW, ng, og, acc);
    store_out(acc, g_y, base, n, ng, og);
}

// ---------------------------------------------------------------------------
// Scatter-add: 16 threads/edge, float4 vector atomics (sm_90+).
// edge_index is INT32 (jax silently downcasts int64).
// ---------------------------------------------------------------------------
__global__ void scatter_kernel(const int* __restrict__ ei, int E, int n) {
    long long t = (long long)blockIdx.x * blockDim.x + threadIdx.x;
    int e = (int)(t >> 4);
    if (e >= E) return;
    int c = (int)(t & 15);
    int row = ei[e];
    int col = ei[E + e];
    if ((unsigned)row >= (unsigned)n || (unsigned)col >= (unsigned)n) return;
    float4 v = reinterpret_cast<const float4*>(g_y + (size_t)row * D)[c];
    atomicAdd(reinterpret_cast<float4*>(g_agg + (size_t)col * D) + c, v);
    if (c == 0) atomicAdd(g_cnt + col, 1);
}

// ---------------------------------------------------------------------------
// Fused epilogue, 256 threads:
//  LN phase: 2 threads per node (each owns 32 features, h = tid>>7),
//    pairwise reductions through 4 smem buffers.
//    a = LN1(agg/cnt); fx = LN2(x + (x-a)*w); concat written k-major to sC.
//  GEMM1 h = relu(C @ W2a^T) -> sC rows 0..63 ; GEMM2 out = h @ W2b^T.
// smem: sC 128*132 + sW 128*68 + sRed 4*256 = 26624 floats = 106496 B
// ---------------------------------------------------------------------------
__global__ __launch_bounds__(NT, 2) void epilogue_kernel(
    const float* __restrict__ x,
    const float* __restrict__ g1, const float* __restrict__ b1,
    const float* __restrict__ wrep,
    const float* __restrict__ g2, const float* __restrict__ b2,
    const float* __restrict__ W2a, const float* __restrict__ W2b,
    float* __restrict__ out, int n)
{
    extern __shared__ __align__(16) float smem[];
    float* sC   = smem;                        // [128][132]
    float* sW   = smem + 128 * CPITCH;         // [128][68]
    float* sRed = smem + 128 * CPITCH + 128 * WPITCH;  // [4][256]
    int tid = threadIdx.x;
    int base = blockIdx.x * 128;
    int ng = tid & 31, og = tid >> 5;

    stage_W<128>(W2a, sW, tid);

    // ---- LN phase: thread owns features [h*32, h*32+32) of node base+(tid&127) ----
    {
        int col = tid & 127;
        int h = tid >> 7;
        int nid = base + col;
        bool valid = nid < n;
        int safe = valid ? nid : 0;

        const u64* pg1 = reinterpret_cast<const u64*>(g1) + h * 16;
        const u64* pb1 = reinterpret_cast<const u64*>(b1) + h * 16;
        const u64* pw  = reinterpret_cast<const u64*>(wrep) + h * 16;
        const u64* pg2 = reinterpret_cast<const u64*>(g2) + h * 16;
        const u64* pb2 = reinterpret_cast<const u64*>(b2) + h * 16;

        u64 a2[16];
        float inv = valid ? 1.0f / fmaxf((float)g_cnt[nid], 1.0f) : 0.f;
        u64 inv2 = dup2(inv);
        const ulonglong2* sp = reinterpret_cast<const ulonglong2*>(g_agg + (size_t)safe * D + h * 32);
        const ulonglong2* xp = reinterpret_cast<const ulonglong2*>(x + (size_t)safe * D + h * 32);
#pragma unroll
        for (int q = 0; q < 8; q++) {
            ulonglong2 v = sp[q];
            a2[2 * q] = mul2(v.x, inv2); a2[2 * q + 1] = mul2(v.y, inv2);
        }
        // LN1 mean
        u64 s = 0ULL;
#pragma unroll
        for (int i = 0; i < 16; i++) s = add2(s, a2[i]);
        sRed[tid] = hsum2(s);
        __syncthreads();
        float m1 = (sRed[tid] + sRed[tid ^ 128]) * (1.f / 64.f);
        u64 mneg = dup2(-m1);
        u64 vs = 0ULL;
#pragma unroll
        for (int i = 0; i < 16; i++) { u64 d = add2(a2[i], mneg); vs = fma2(d, d, vs); }
        sRed[256 + tid] = hsum2(vs);
        __syncthreads();
        float r1 = rsqrtf((sRed[256 + tid] + sRed[256 + (tid ^ 128)]) * (1.f / 64.f) + 1e-5f);
        u64 r12 = dup2(r1);
#pragma unroll
        for (int i = 0; i < 16; i++)
            a2[i] = fma2(mul2(add2(a2[i], mneg), r12), pg1[i], pb1[i]);

        // fx = x + (x - a)*w, then LN2
        u64 f2[16];
#pragma unroll
        for (int q = 0; q < 8; q++) {
            ulonglong2 v = xp[q];
            u64 vx = valid ? v.x : 0ULL, vy = valid ? v.y : 0ULL;
            u64 d0 = add2(vx, neg2(a2[2 * q]));
            u64 d1 = add2(vy, neg2(a2[2 * q + 1]));
            f2[2 * q]     = fma2(d0, pw[2 * q], vx);
            f2[2 * q + 1] = fma2(d1, pw[2 * q + 1], vy);
        }
        s = 0ULL;
#pragma unroll
        for (int i = 0; i < 16; i++) s = add2(s, f2[i]);
        sRed[512 + tid] = hsum2(s);
        __syncthreads();
        float m2 = (sRed[512 + tid] + sRed[512 + (tid ^ 128)]) * (1.f / 64.f);
        mneg = dup2(-m2);
        vs = 0ULL;
#pragma unroll
        for (int i = 0; i < 16; i++) { u64 d = add2(f2[i], mneg); vs = fma2(d, d, vs); }
        sRed[768 + tid] = hsum2(vs);
        __syncthreads();
        float r2 = rsqrtf((sRed[768 + tid] + sRed[768 + (tid ^ 128)]) * (1.f / 64.f) + 1e-5f);
        u64 r22 = dup2(r2);
#pragma unroll
        for (int i = 0; i < 16; i++)
            f2[i] = fma2(mul2(add2(f2[i], mneg), r22), pg2[i], pb2[i]);

        // write concat tile k-major: rows [0,64) = fx, [64,128) = a
#pragma unroll
        for (int i = 0; i < 16; i++) {
            float lo, hi;
            unpack2(f2[i], lo, hi);
            sC[(h * 32 + 2 * i) * CPITCH + col] = lo;
            sC[(h * 32 + 2 * i + 1) * CPITCH + col] = hi;
            unpack2(a2[i], lo, hi);
            sC[(64 + h * 32 + 2 * i) * CPITCH + col] = lo;
            sC[(64 + h * 32 + 2 * i + 1) * CPITCH + col] = hi;
        }
    }
    __syncthreads();

    u64 acc[4][4];
    gemm_tile<128>(sC, sW, ng, og, acc);
    __syncthreads();

    relu_to_smem(acc, sC, ng, og);      // hidden tile in sC rows 0..63
    stage_W<64>(W2b, sW, tid);
    __syncthreads();

    gemm_tile<64>(sC, sW, ng, og, acc);
    store_out(acc, out, base, n, ng, og);
}

// ---------------------------------------------------------------------------
// Launch
// ---------------------------------------------------------------------------
extern "C" void kernel_launch(void* const* d_in, const int* in_sizes, int n_in,
                              void* d_out, int out_size) {
    const float* x   = (const float*)d_in[0];
    const int*   ei  = (const int*)d_in[1];      // int32 (jax downcasts int64)
    const float* W1a = (const float*)d_in[2];
    const float* W1b = (const float*)d_in[3];
    const float* g1  = (const float*)d_in[4];
    const float* b1  = (const float*)d_in[5];
    const float* w   = (const float*)d_in[6];
    const float* g2  = (const float*)d_in[7];
    const float* b2  = (const float*)d_in[8];
    const float* W2a = (const float*)d_in[9];
    const float* W2b = (const float*)d_in[10];
    float* out = (float*)d_out;

    int n = in_sizes[0] / D;
    int E = in_sizes[1] / 2;
    int blocks = (n + 127) / 128;

    const int MLP1_SMEM = (64 * CPITCH + 64 * WPITCH) * 4;                  // 51200 B
    const int EPI_SMEM  = (128 * CPITCH + 128 * WPITCH + 4 * 256) * 4;      // 106496 B
    cudaFuncSetAttribute(mlp1_kernel, cudaFuncAttributeMaxDynamicSharedMemorySize, MLP1_SMEM);
    cudaFuncSetAttribute(epilogue_kernel, cudaFuncAttributeMaxDynamicSharedMemorySize, EPI_SMEM);

    mlp1_kernel<<<blocks, NT, MLP1_SMEM>>>(x, W1a, W1b, n);
    {
        long long total = (long long)E * 16;
        int sblocks = (int)((total + 255) / 256);
        scatter_kernel<<<sblocks, 256>>>(ei, E, n);
    }
    epilogue_kernel<<<blocks, NT, EPI_SMEM>>>(x, g1, b1, w, g2, b2, W2a, W2b, out, n);
}